// round 1
// baseline (speedup 1.0000x reference)
#include <cuda_runtime.h>
#include <math_constants.h>

// ---------------------------------------------------------------------------
// Problem constants: B=4, N=2048, D_MODEL=1024, H=16, Dh=64
// qkv buffer layout: [B, N, 3*1024], cols [0,1024)=Q, [1024,2048)=K, [2048,3072)=V
// head h occupies cols h*64 .. h*64+63 within each third.
// ---------------------------------------------------------------------------

#define BATCH 4
#define SEQ   2048
#define DM    1024
#define NHEAD 16
#define DH    64
#define MROWS (BATCH * SEQ)   // 8192

// Scratch (allocation-free rule: __device__ globals)
__device__ float g_qkv[(size_t)MROWS * 3 * DM];   // 100.7 MB
__device__ float g_att[(size_t)MROWS * DM];       // 33.6 MB

// ---------------------------------------------------------------------------
// SGEMM + bias:  C[M,N] = A[M,K] @ B[K,N] + bias[N]
// 128x128 tile, BK=8, 256 threads, 8x8 per-thread microtile.
// M,N,K all multiples of 128/8 here -> no bounds checks.
// ---------------------------------------------------------------------------
__global__ __launch_bounds__(256)
void sgemm_bias_kernel(const float* __restrict__ A,
                       const float* __restrict__ B,
                       const float* __restrict__ bias,
                       float* __restrict__ C,
                       int M, int N, int K)
{
    __shared__ float As[8][128];
    __shared__ float Bs[8][128];

    const int tid = threadIdx.x;
    const int tx = tid & 15;        // 0..15, columns
    const int ty = tid >> 4;        // 0..15, rows
    const int row0 = blockIdx.y * 128;
    const int col0 = blockIdx.x * 128;

    const int arow = tid >> 1;             // 0..127
    const int acol = (tid & 1) * 4;        // 0 or 4
    const int brow = tid >> 5;             // 0..7
    const int bcol = (tid & 31) * 4;       // 0..124

    const float* Aptr = A + (size_t)(row0 + arow) * K + acol;
    const float* Bptr = B + (size_t)brow * N + col0 + bcol;

    float c[8][8];
#pragma unroll
    for (int i = 0; i < 8; i++)
#pragma unroll
        for (int j = 0; j < 8; j++) c[i][j] = 0.0f;

    for (int k0 = 0; k0 < K; k0 += 8) {
        float4 av = *(const float4*)(Aptr + k0);
        As[acol + 0][arow] = av.x;
        As[acol + 1][arow] = av.y;
        As[acol + 2][arow] = av.z;
        As[acol + 3][arow] = av.w;
        *(float4*)&Bs[brow][bcol] = *(const float4*)(Bptr + (size_t)k0 * N);
        __syncthreads();

#pragma unroll
        for (int kk = 0; kk < 8; kk++) {
            float4 a0 = *(float4*)&As[kk][ty * 8];
            float4 a1 = *(float4*)&As[kk][ty * 8 + 4];
            float4 b0 = *(float4*)&Bs[kk][tx * 8];
            float4 b1 = *(float4*)&Bs[kk][tx * 8 + 4];
            float ar[8] = {a0.x, a0.y, a0.z, a0.w, a1.x, a1.y, a1.z, a1.w};
            float br[8] = {b0.x, b0.y, b0.z, b0.w, b1.x, b1.y, b1.z, b1.w};
#pragma unroll
            for (int i = 0; i < 8; i++)
#pragma unroll
                for (int j = 0; j < 8; j++)
                    c[i][j] = fmaf(ar[i], br[j], c[i][j]);
        }
        __syncthreads();
    }

    float bv[8];
#pragma unroll
    for (int j = 0; j < 8; j++) bv[j] = bias[col0 + tx * 8 + j];

#pragma unroll
    for (int i = 0; i < 8; i++) {
        float* crow = C + (size_t)(row0 + ty * 8 + i) * N + col0 + tx * 8;
        float4 w0 = make_float4(c[i][0] + bv[0], c[i][1] + bv[1],
                                c[i][2] + bv[2], c[i][3] + bv[3]);
        float4 w1 = make_float4(c[i][4] + bv[4], c[i][5] + bv[5],
                                c[i][6] + bv[6], c[i][7] + bv[7]);
        *(float4*)(crow) = w0;
        *(float4*)(crow + 4) = w1;
    }
}

// ---------------------------------------------------------------------------
// Flash attention (causal), fp32, online softmax.
// grid = (N/64, H, B); 256 threads as 16x16; each thread owns 4x4 of the
// 64x64 S tile and 4x4 of the 64x64 O tile (rows match -> shared row stats).
// Shared: Qs[d][i], KP[d][j] (K, later reused as P[j][i]), Vs[j][dim].
// ---------------------------------------------------------------------------
#define TS  64
#define PAD 68   // 68*4B = 272B, 16B aligned rows, spreads transpose-store banks

__global__ __launch_bounds__(256)
void flash_attn_kernel(const float* __restrict__ qkv, float* __restrict__ out)
{
    extern __shared__ float sm[];
    float* Qs = sm;                 // [64][PAD], d-major: Qs[d*PAD + i]
    float* KP = sm + TS * PAD;      // K d-major, then P j-major
    float* Vs = sm + 2 * TS * PAD;  // [64][PAD], j-major: Vs[j*PAD + dim]

    const int qt = blockIdx.x;
    const int h  = blockIdx.y;
    const int b  = blockIdx.z;
    const int tid = threadIdx.x;
    const int tx = tid & 15;
    const int ty = tid >> 4;
    const int q0 = qt * TS;
    const float scale = 0.125f;   // 1/sqrt(64)

    const float* Qg = qkv + (size_t)b * SEQ * (3 * DM) + h * DH;
    const float* Kg = Qg + DM;
    const float* Vg = Qg + 2 * DM;

    // loader mapping: 4 threads per row, each covers 16 floats of Dh=64
    const int lr = tid >> 2;            // 0..63 (row within tile)
    const int ld = (tid & 3) * 16;      // d segment start

    // Load Q tile, transposed into Qs[d][i]
    {
        const float* src = Qg + (size_t)(q0 + lr) * (3 * DM) + ld;
#pragma unroll
        for (int g = 0; g < 4; g++) {
            float4 v = *(const float4*)(src + g * 4);
            int d = ld + g * 4;
            Qs[(d + 0) * PAD + lr] = v.x;
            Qs[(d + 1) * PAD + lr] = v.y;
            Qs[(d + 2) * PAD + lr] = v.z;
            Qs[(d + 3) * PAD + lr] = v.w;
        }
    }

    float m[4], l[4], o[4][4];
#pragma unroll
    for (int i = 0; i < 4; i++) {
        m[i] = -CUDART_INF_F;
        l[i] = 0.0f;
#pragma unroll
        for (int j = 0; j < 4; j++) o[i][j] = 0.0f;
    }
    __syncthreads();

    for (int kt = 0; kt <= qt; kt++) {
        const int k0 = kt * TS;
        // Load K (transposed) and V tiles
        {
            const float* ks = Kg + (size_t)(k0 + lr) * (3 * DM) + ld;
#pragma unroll
            for (int g = 0; g < 4; g++) {
                float4 v = *(const float4*)(ks + g * 4);
                int d = ld + g * 4;
                KP[(d + 0) * PAD + lr] = v.x;
                KP[(d + 1) * PAD + lr] = v.y;
                KP[(d + 2) * PAD + lr] = v.z;
                KP[(d + 3) * PAD + lr] = v.w;
            }
            const float* vsrc = Vg + (size_t)(k0 + lr) * (3 * DM) + ld;
#pragma unroll
            for (int g = 0; g < 4; g++)
                *(float4*)&Vs[lr * PAD + ld + g * 4] = *(const float4*)(vsrc + g * 4);
        }
        __syncthreads();

        // S = (Q @ K^T) * scale
        float s[4][4];
#pragma unroll
        for (int i = 0; i < 4; i++)
#pragma unroll
            for (int j = 0; j < 4; j++) s[i][j] = 0.0f;

#pragma unroll 8
        for (int d = 0; d < TS; d++) {
            float4 a = *(float4*)&Qs[d * PAD + ty * 4];
            float4 bb = *(float4*)&KP[d * PAD + tx * 4];
            float ar[4] = {a.x, a.y, a.z, a.w};
            float br[4] = {bb.x, bb.y, bb.z, bb.w};
#pragma unroll
            for (int i = 0; i < 4; i++)
#pragma unroll
                for (int j = 0; j < 4; j++)
                    s[i][j] = fmaf(ar[i], br[j], s[i][j]);
        }

        if (kt == qt) {
            // diagonal tile: mask j > i (global offsets equal)
#pragma unroll
            for (int i = 0; i < 4; i++)
#pragma unroll
                for (int j = 0; j < 4; j++)
                    s[i][j] = (tx * 4 + j > ty * 4 + i) ? -1e30f
                                                        : s[i][j] * scale;
        } else {
#pragma unroll
            for (int i = 0; i < 4; i++)
#pragma unroll
                for (int j = 0; j < 4; j++) s[i][j] *= scale;
        }

        // Online softmax: 16 lanes (same ty) own each row group; xor<=8 stays
        // within the 16-lane half-warp.
#pragma unroll
        for (int i = 0; i < 4; i++) {
            float rm = fmaxf(fmaxf(s[i][0], s[i][1]), fmaxf(s[i][2], s[i][3]));
#pragma unroll
            for (int off = 8; off >= 1; off >>= 1)
                rm = fmaxf(rm, __shfl_xor_sync(0xffffffffu, rm, off));
            float mn = fmaxf(m[i], rm);
            float corr = __expf(m[i] - mn);
            float ls = 0.0f;
#pragma unroll
            for (int j = 0; j < 4; j++) {
                float p = __expf(s[i][j] - mn);
                s[i][j] = p;
                ls += p;
            }
#pragma unroll
            for (int off = 8; off >= 1; off >>= 1)
                ls += __shfl_xor_sync(0xffffffffu, ls, off);
            l[i] = l[i] * corr + ls;
#pragma unroll
            for (int j = 0; j < 4; j++) o[i][j] *= corr;
            m[i] = mn;
        }

        __syncthreads();   // everyone done reading K from KP
        // Store P transposed: P[j][i]
#pragma unroll
        for (int i = 0; i < 4; i++)
#pragma unroll
            for (int j = 0; j < 4; j++)
                KP[(tx * 4 + j) * PAD + ty * 4 + i] = s[i][j];
        __syncthreads();

        // O += P @ V
#pragma unroll 8
        for (int j = 0; j < TS; j++) {
            float4 p4 = *(float4*)&KP[j * PAD + ty * 4];
            float4 v4 = *(float4*)&Vs[j * PAD + tx * 4];
            float pr[4] = {p4.x, p4.y, p4.z, p4.w};
            float vr[4] = {v4.x, v4.y, v4.z, v4.w};
#pragma unroll
            for (int i = 0; i < 4; i++)
#pragma unroll
                for (int c = 0; c < 4; c++)
                    o[i][c] = fmaf(pr[i], vr[c], o[i][c]);
        }
        __syncthreads();   // before next iteration overwrites KP/Vs
    }

    // Normalize and write [b, n, h*64 + dim]
#pragma unroll
    for (int i = 0; i < 4; i++) {
        float inv = 1.0f / l[i];
        float4 w = make_float4(o[i][0] * inv, o[i][1] * inv,
                               o[i][2] * inv, o[i][3] * inv);
        float* dst = out + (size_t)(b * SEQ + q0 + ty * 4 + i) * DM
                         + h * DH + tx * 4;
        *(float4*)dst = w;
    }
}

// ---------------------------------------------------------------------------
// kernel_launch
// inputs: [0]=input f32[4,2048,1024], [1]=W_qkv[1024,3072], [2]=b_qkv[3072],
//         [3]=W_out[1024,1024], [4]=b_out[1024], [5]=mask (ignored; causal)
// ---------------------------------------------------------------------------
extern "C" void kernel_launch(void* const* d_in, const int* in_sizes, int n_in,
                              void* d_out, int out_size)
{
    const float* inp  = (const float*)d_in[0];
    const float* Wqkv = (const float*)d_in[1];
    const float* bqkv = (const float*)d_in[2];
    const float* Wout = (const float*)d_in[3];
    const float* bout = (const float*)d_in[4];
    float* out = (float*)d_out;

    float *qkv, *att;
    cudaGetSymbolAddress((void**)&qkv, g_qkv);
    cudaGetSymbolAddress((void**)&att, g_att);

    const int smem_flash = 3 * TS * PAD * (int)sizeof(float);  // 52224 B
    cudaFuncSetAttribute(flash_attn_kernel,
                         cudaFuncAttributeMaxDynamicSharedMemorySize, smem_flash);

    // 1. QKV projection: [8192,1024] @ [1024,3072] + b
    dim3 g1(3 * DM / 128, MROWS / 128);
    sgemm_bias_kernel<<<g1, 256>>>(inp, Wqkv, bqkv, qkv, MROWS, 3 * DM, DM);

    // 2. Causal flash attention per (q-tile, head, batch)
    dim3 gf(SEQ / TS, NHEAD, BATCH);
    flash_attn_kernel<<<gf, 256, smem_flash>>>(qkv, att);

    // 3. Output projection: [8192,1024] @ [1024,1024] + b
    dim3 g2(DM / 128, MROWS / 128);
    sgemm_bias_kernel<<<g2, 256>>>(att, Wout, bout, out, MROWS, DM, DM);
}

// round 6
// speedup vs baseline: 1.1955x; 1.1955x over previous
#include <cuda_runtime.h>
#include <cuda_bf16.h>
#include <cstdint>
#include <math_constants.h>

// Problem constants: B=4, N=2048, D_MODEL=1024, H=16, Dh=64
#define BATCH 4
#define SEQ   2048
#define DM    1024
#define NHEAD 16
#define DH    64
#define MROWS (BATCH * SEQ)

typedef unsigned int u32;

__device__ float g_qkv[(size_t)MROWS * 3 * DM];
__device__ float g_att[(size_t)MROWS * DM];

// ===========================================================================
// bf16-split tensor-core GEMM: C = A @ B + bias.
// Each fp32 operand x = hi + lo, both bf16. Product uses 3 MMAs:
// hi*hi + hi*lo + lo*hi; dropped lo*lo term is ~2^-18 relative.
// 128x128 CTA tile, BK=32, 256 threads = 8 warps as 4 row x 2 col,
// warp tile 32x64 via mma.sync m16n8k16 row.col f32.bf16.bf16.f32.
// ===========================================================================

#define PA 40
#define PB 136

__device__ __forceinline__ void ldsm_x4(u32* r, u32 addr) {
    asm volatile("ldmatrix.sync.aligned.m8n8.x4.shared.b16 {%0,%1,%2,%3},[%4];"
                 : "=r"(r[0]), "=r"(r[1]), "=r"(r[2]), "=r"(r[3]) : "r"(addr));
}
__device__ __forceinline__ void ldsm_x4_t(u32* r, u32 addr) {
    asm volatile("ldmatrix.sync.aligned.m8n8.x4.trans.shared.b16 {%0,%1,%2,%3},[%4];"
                 : "=r"(r[0]), "=r"(r[1]), "=r"(r[2]), "=r"(r[3]) : "r"(addr));
}
__device__ __forceinline__ void mma16816(float* c, const u32* a,
                                         u32 b0, u32 b1) {
    asm volatile(
        "mma.sync.aligned.m16n8k16.row.col.f32.bf16.bf16.f32 "
        "{%0,%1,%2,%3},{%4,%5,%6,%7},{%8,%9},{%0,%1,%2,%3};"
        : "+f"(c[0]), "+f"(c[1]), "+f"(c[2]), "+f"(c[3])
        : "r"(a[0]), "r"(a[1]), "r"(a[2]), "r"(a[3]), "r"(b0), "r"(b1));
}

__device__ __forceinline__ void split_store(__nv_bfloat16* hi_p, __nv_bfloat16* lo_p,
                                            float x) {
    __nv_bfloat16 h = __float2bfloat16(x);
    __nv_bfloat16 l = __float2bfloat16(x - __bfloat162float(h));
    *hi_p = h;
    *lo_p = l;
}

__global__ __launch_bounds__(256, 1)
void gemm_bf16split_bias(const float* __restrict__ A,
                         const float* __restrict__ B,
                         const float* __restrict__ bias,
                         float* __restrict__ C,
                         int M, int N, int K)
{
    // index 0 = hi part, index 1 = lo part
    __shared__ __nv_bfloat16 sA[2][128 * PA];
    __shared__ __nv_bfloat16 sB[2][32 * PB];

    const int tid  = threadIdx.x;
    const int lane = tid & 31;
    const int warp = tid >> 5;
    const int wm   = warp & 3;
    const int wn   = warp >> 2;
    const int row0 = blockIdx.y * 128;
    const int col0 = blockIdx.x * 128;

    // global load mapping: A loads 16 floats per thread, 2 threads per row;
    // B loads 16 floats per thread, 8 threads per row
    const int arow = tid >> 1;
    const int acol = (tid & 1) * 16;
    const int brow = tid >> 3;
    const int bcol = (tid & 7) * 16;

    const float* Ag = A + (size_t)(row0 + arow) * K + acol;
    const float* Bg = B + (size_t)brow * N + col0 + bcol;

    // accumulators: 2 m-blocks of 16 rows, 8 n-frags of 8 cols, 4 regs each
    float c[2][8][4];
#pragma unroll
    for (int mi = 0; mi < 2; mi++)
#pragma unroll
        for (int j = 0; j < 8; j++)
#pragma unroll
            for (int e = 0; e < 4; e++) c[mi][j][e] = 0.0f;

    u32 sA_u32[2];
    u32 sB_u32[2];
    sA_u32[0] = (u32)__cvta_generic_to_shared(&sA[0][0]);
    sA_u32[1] = (u32)__cvta_generic_to_shared(&sA[1][0]);
    sB_u32[0] = (u32)__cvta_generic_to_shared(&sB[0][0]);
    sB_u32[1] = (u32)__cvta_generic_to_shared(&sB[1][0]);

    const int lrow = lane & 15;
    const int lsel = lane >> 4;

    // per-lane ldmatrix byte offsets; kk-step adjustment added in the loop
    u32 aoff0 = (u32)(((wm * 32 + lrow) * PA + lsel * 8) * 2);
    u32 aoff1 = (u32)(((wm * 32 + 16 + lrow) * PA + lsel * 8) * 2);
    u32 boff0 = (u32)((lrow * PB + wn * 64 + lsel * 8) * 2);
    u32 boff1 = boff0 + 16 * 2;
    u32 boff2 = boff0 + 32 * 2;
    u32 boff3 = boff0 + 48 * 2;

    const int T = K / 32;
    float4 ra[4];
    float4 rb[4];

#pragma unroll
    for (int i = 0; i < 4; i++) ra[i] = *(const float4*)(Ag + i * 4);
#pragma unroll
    for (int i = 0; i < 4; i++) rb[i] = *(const float4*)(Bg + i * 4);

    for (int t = 0; t < T; t++) {
        // convert fp32 to bf16 hi plus lo and store to shared
        {
            float av[16] = {ra[0].x, ra[0].y, ra[0].z, ra[0].w,
                            ra[1].x, ra[1].y, ra[1].z, ra[1].w,
                            ra[2].x, ra[2].y, ra[2].z, ra[2].w,
                            ra[3].x, ra[3].y, ra[3].z, ra[3].w};
            float bv[16] = {rb[0].x, rb[0].y, rb[0].z, rb[0].w,
                            rb[1].x, rb[1].y, rb[1].z, rb[1].w,
                            rb[2].x, rb[2].y, rb[2].z, rb[2].w,
                            rb[3].x, rb[3].y, rb[3].z, rb[3].w};
            __nv_bfloat16* a_hi = &sA[0][arow * PA + acol];
            __nv_bfloat16* a_lo = &sA[1][arow * PA + acol];
            __nv_bfloat16* b_hi = &sB[0][brow * PB + bcol];
            __nv_bfloat16* b_lo = &sB[1][brow * PB + bcol];
#pragma unroll
            for (int i = 0; i < 16; i++) split_store(a_hi + i, a_lo + i, av[i]);
#pragma unroll
            for (int i = 0; i < 16; i++) split_store(b_hi + i, b_lo + i, bv[i]);
        }
        __syncthreads();

        // prefetch next k-tile into registers
        if (t + 1 < T) {
            const float* Ap = Ag + (t + 1) * 32;
            const float* Bp = Bg + (size_t)(t + 1) * 32 * N;
#pragma unroll
            for (int i = 0; i < 4; i++) ra[i] = *(const float4*)(Ap + i * 4);
#pragma unroll
            for (int i = 0; i < 4; i++) rb[i] = *(const float4*)(Bp + i * 4);
        }

        // compute: two k16 steps per k32 tile
#pragma unroll
        for (int kk = 0; kk < 2; kk++) {
            u32 afr[2][2][4];
            u32 bfr[2][4][4];
            const u32 ak = (u32)(kk * 32);
            const u32 bk = (u32)(kk * 16 * PB * 2);
#pragma unroll
            for (int h = 0; h < 2; h++) {
                ldsm_x4(afr[h][0], sA_u32[h] + aoff0 + ak);
                ldsm_x4(afr[h][1], sA_u32[h] + aoff1 + ak);
                ldsm_x4_t(bfr[h][0], sB_u32[h] + boff0 + bk);
                ldsm_x4_t(bfr[h][1], sB_u32[h] + boff1 + bk);
                ldsm_x4_t(bfr[h][2], sB_u32[h] + boff2 + bk);
                ldsm_x4_t(bfr[h][3], sB_u32[h] + boff3 + bk);
            }

#pragma unroll
            for (int j = 0; j < 8; j++) {
                const int g = j >> 1;
                const int o = (j & 1) * 2;
#pragma unroll
                for (int mi = 0; mi < 2; mi++) {
                    mma16816(c[mi][j], afr[0][mi], bfr[0][g][o], bfr[0][g][o + 1]);
                    mma16816(c[mi][j], afr[0][mi], bfr[1][g][o], bfr[1][g][o + 1]);
                    mma16816(c[mi][j], afr[1][mi], bfr[0][g][o], bfr[0][g][o + 1]);
                }
            }
        }
        __syncthreads();
    }

    // epilogue: add bias, store fp32
    const int crow = lane >> 2;
    const int ccol = (lane & 3) * 2;
#pragma unroll
    for (int j = 0; j < 8; j++) {
        const int col = col0 + wn * 64 + j * 8 + ccol;
        const float2 bb = *(const float2*)(bias + col);
#pragma unroll
        for (int mi = 0; mi < 2; mi++) {
            const int r = row0 + wm * 32 + mi * 16 + crow;
            float2 v0 = make_float2(c[mi][j][0] + bb.x, c[mi][j][1] + bb.y);
            float2 v1 = make_float2(c[mi][j][2] + bb.x, c[mi][j][3] + bb.y);
            *(float2*)(C + (size_t)r * N + col) = v0;
            *(float2*)(C + (size_t)(r + 8) * N + col) = v1;
        }
    }
}

// ---------------------------------------------------------------------------
// Flash attention, causal, fp32, online softmax. Unchanged from round 1.
// ---------------------------------------------------------------------------
#define TS  64
#define PAD 68

__global__ __launch_bounds__(256)
void flash_attn_kernel(const float* __restrict__ qkv, float* __restrict__ out)
{
    extern __shared__ float sm[];
    float* Qs = sm;
    float* KP = sm + TS * PAD;
    float* Vs = sm + 2 * TS * PAD;

    const int qt = blockIdx.x;
    const int h  = blockIdx.y;
    const int b  = blockIdx.z;
    const int tid = threadIdx.x;
    const int tx = tid & 15;
    const int ty = tid >> 4;
    const int q0 = qt * TS;
    const float scale = 0.125f;

    const float* Qg = qkv + (size_t)b * SEQ * (3 * DM) + h * DH;
    const float* Kg = Qg + DM;
    const float* Vg = Qg + 2 * DM;

    const int lr = tid >> 2;
    const int ld = (tid & 3) * 16;

    {
        const float* src = Qg + (size_t)(q0 + lr) * (3 * DM) + ld;
#pragma unroll
        for (int g = 0; g < 4; g++) {
            float4 v = *(const float4*)(src + g * 4);
            int d = ld + g * 4;
            Qs[(d + 0) * PAD + lr] = v.x;
            Qs[(d + 1) * PAD + lr] = v.y;
            Qs[(d + 2) * PAD + lr] = v.z;
            Qs[(d + 3) * PAD + lr] = v.w;
        }
    }

    float m[4];
    float l[4];
    float o[4][4];
#pragma unroll
    for (int i = 0; i < 4; i++) {
        m[i] = -CUDART_INF_F;
        l[i] = 0.0f;
#pragma unroll
        for (int j = 0; j < 4; j++) o[i][j] = 0.0f;
    }
    __syncthreads();

    for (int kt = 0; kt <= qt; kt++) {
        const int k0 = kt * TS;
        {
            const float* ks = Kg + (size_t)(k0 + lr) * (3 * DM) + ld;
#pragma unroll
            for (int g = 0; g < 4; g++) {
                float4 v = *(const float4*)(ks + g * 4);
                int d = ld + g * 4;
                KP[(d + 0) * PAD + lr] = v.x;
                KP[(d + 1) * PAD + lr] = v.y;
                KP[(d + 2) * PAD + lr] = v.z;
                KP[(d + 3) * PAD + lr] = v.w;
            }
            const float* vsrc = Vg + (size_t)(k0 + lr) * (3 * DM) + ld;
#pragma unroll
            for (int g = 0; g < 4; g++)
                *(float4*)&Vs[lr * PAD + ld + g * 4] = *(const float4*)(vsrc + g * 4);
        }
        __syncthreads();

        float s[4][4];
#pragma unroll
        for (int i = 0; i < 4; i++)
#pragma unroll
            for (int j = 0; j < 4; j++) s[i][j] = 0.0f;

#pragma unroll 8
        for (int d = 0; d < TS; d++) {
            float4 a = *(float4*)&Qs[d * PAD + ty * 4];
            float4 bb = *(float4*)&KP[d * PAD + tx * 4];
            float ar[4] = {a.x, a.y, a.z, a.w};
            float br[4] = {bb.x, bb.y, bb.z, bb.w};
#pragma unroll
            for (int i = 0; i < 4; i++)
#pragma unroll
                for (int j = 0; j < 4; j++)
                    s[i][j] = fmaf(ar[i], br[j], s[i][j]);
        }

        if (kt == qt) {
#pragma unroll
            for (int i = 0; i < 4; i++)
#pragma unroll
                for (int j = 0; j < 4; j++)
                    s[i][j] = (tx * 4 + j > ty * 4 + i) ? -1e30f
                                                        : s[i][j] * scale;
        } else {
#pragma unroll
            for (int i = 0; i < 4; i++)
#pragma unroll
                for (int j = 0; j < 4; j++) s[i][j] *= scale;
        }

#pragma unroll
        for (int i = 0; i < 4; i++) {
            float rm = fmaxf(fmaxf(s[i][0], s[i][1]), fmaxf(s[i][2], s[i][3]));
#pragma unroll
            for (int off = 8; off >= 1; off >>= 1)
                rm = fmaxf(rm, __shfl_xor_sync(0xffffffffu, rm, off));
            float mn = fmaxf(m[i], rm);
            float corr = __expf(m[i] - mn);
            float ls = 0.0f;
#pragma unroll
            for (int j = 0; j < 4; j++) {
                float p = __expf(s[i][j] - mn);
                s[i][j] = p;
                ls += p;
            }
#pragma unroll
            for (int off = 8; off >= 1; off >>= 1)
                ls += __shfl_xor_sync(0xffffffffu, ls, off);
            l[i] = l[i] * corr + ls;
#pragma unroll
            for (int j = 0; j < 4; j++) o[i][j] *= corr;
            m[i] = mn;
        }

        __syncthreads();
#pragma unroll
        for (int i = 0; i < 4; i++)
#pragma unroll
            for (int j = 0; j < 4; j++)
                KP[(tx * 4 + j) * PAD + ty * 4 + i] = s[i][j];
        __syncthreads();

#pragma unroll 8
        for (int j = 0; j < TS; j++) {
            float4 p4 = *(float4*)&KP[j * PAD + ty * 4];
            float4 v4 = *(float4*)&Vs[j * PAD + tx * 4];
            float pr[4] = {p4.x, p4.y, p4.z, p4.w};
            float vr[4] = {v4.x, v4.y, v4.z, v4.w};
#pragma unroll
            for (int i = 0; i < 4; i++)
#pragma unroll
                for (int cidx = 0; cidx < 4; cidx++)
                    o[i][cidx] = fmaf(pr[i], vr[cidx], o[i][cidx]);
        }
        __syncthreads();
    }

#pragma unroll
    for (int i = 0; i < 4; i++) {
        float inv = 1.0f / l[i];
        float4 w = make_float4(o[i][0] * inv, o[i][1] * inv,
                               o[i][2] * inv, o[i][3] * inv);
        float* dst = out + (size_t)(b * SEQ + q0 + ty * 4 + i) * DM
                         + h * DH + tx * 4;
        *(float4*)dst = w;
    }
}

extern "C" void kernel_launch(void* const* d_in, const int* in_sizes, int n_in,
                              void* d_out, int out_size)
{
    const float* inp  = (const float*)d_in[0];
    const float* Wqkv = (const float*)d_in[1];
    const float* bqkv = (const float*)d_in[2];
    const float* Wout = (const float*)d_in[3];
    const float* bout = (const float*)d_in[4];
    float* out = (float*)d_out;

    float* qkv;
    float* att;
    cudaGetSymbolAddress((void**)&qkv, g_qkv);
    cudaGetSymbolAddress((void**)&att, g_att);

    const int smem_flash = 3 * TS * PAD * (int)sizeof(float);
    cudaFuncSetAttribute(flash_attn_kernel,
                         cudaFuncAttributeMaxDynamicSharedMemorySize, smem_flash);

    dim3 g1(3 * DM / 128, MROWS / 128);
    gemm_bf16split_bias<<<g1, 256>>>(inp, Wqkv, bqkv, qkv, MROWS, 3 * DM, DM);

    dim3 gf(SEQ / TS, NHEAD, BATCH);
    flash_attn_kernel<<<gf, 256, smem_flash>>>(qkv, att);

    dim3 g2(DM / 128, MROWS / 128);
    gemm_bf16split_bias<<<g2, 256>>>(att, Wout, bout, out, MROWS, DM, DM);
}

// round 8
// speedup vs baseline: 2.8096x; 2.3501x over previous
#include <cuda_runtime.h>
#include <cuda_bf16.h>
#include <math_constants.h>

#define BATCH 4
#define SEQ   2048
#define DM    1024
#define NHEAD 16
#define DH    64
#define MROWS 8192

typedef unsigned int u32;

// split scratch buffers in device globals
__device__ __nv_bfloat16 g_inp_h[(size_t)MROWS * DM];
__device__ __nv_bfloat16 g_inp_l[(size_t)MROWS * DM];
__device__ __nv_bfloat16 g_wq_h[(size_t)DM * 3 * DM];
__device__ __nv_bfloat16 g_wq_l[(size_t)DM * 3 * DM];
__device__ __nv_bfloat16 g_wo_h[(size_t)DM * DM];
__device__ __nv_bfloat16 g_wo_l[(size_t)DM * DM];
__device__ __nv_bfloat16 g_qkv_h[(size_t)MROWS * 3 * DM];
__device__ __nv_bfloat16 g_qkv_l[(size_t)MROWS * 3 * DM];
__device__ __nv_bfloat16 g_att_h[(size_t)MROWS * DM];
__device__ __nv_bfloat16 g_att_l[(size_t)MROWS * DM];

// ---------------------------------------------------------------------------
// helpers
// ---------------------------------------------------------------------------
__device__ __forceinline__ void ldsm_x4(u32* r, u32 addr) {
    asm volatile("ldmatrix.sync.aligned.m8n8.x4.shared.b16 {%0,%1,%2,%3},[%4];"
                 : "=r"(r[0]), "=r"(r[1]), "=r"(r[2]), "=r"(r[3]) : "r"(addr));
}
__device__ __forceinline__ void ldsm_x4_t(u32* r, u32 addr) {
    asm volatile("ldmatrix.sync.aligned.m8n8.x4.trans.shared.b16 {%0,%1,%2,%3},[%4];"
                 : "=r"(r[0]), "=r"(r[1]), "=r"(r[2]), "=r"(r[3]) : "r"(addr));
}
__device__ __forceinline__ void mma16816(float* c, const u32* a,
                                         u32 b0, u32 b1) {
    asm volatile(
        "mma.sync.aligned.m16n8k16.row.col.f32.bf16.bf16.f32 "
        "{%0,%1,%2,%3},{%4,%5,%6,%7},{%8,%9},{%0,%1,%2,%3};"
        : "+f"(c[0]), "+f"(c[1]), "+f"(c[2]), "+f"(c[3])
        : "r"(a[0]), "r"(a[1]), "r"(a[2]), "r"(a[3]), "r"(b0), "r"(b1));
}
__device__ __forceinline__ void cp16(u32 dst, const void* src) {
    asm volatile("cp.async.ca.shared.global [%0], [%1], 16;" :: "r"(dst), "l"(src));
}
__device__ __forceinline__ void cp_commit() {
    asm volatile("cp.async.commit_group;");
}
template <int N> __device__ __forceinline__ void cp_wait() {
    asm volatile("cp.async.wait_group %0;" :: "n"(N));
}
__device__ __forceinline__ u32 packbf2(__nv_bfloat16 a, __nv_bfloat16 b) {
    __nv_bfloat162 t;
    t.x = a;
    t.y = b;
    return *reinterpret_cast<u32*>(&t);
}
// split two fp32 into packed hi pair and packed lo pair
__device__ __forceinline__ void split2(float a, float b, u32* hi, u32* lo) {
    __nv_bfloat16 ha = __float2bfloat16(a);
    __nv_bfloat16 hb = __float2bfloat16(b);
    __nv_bfloat16 la = __float2bfloat16(a - __bfloat162float(ha));
    __nv_bfloat16 lb = __float2bfloat16(b - __bfloat162float(hb));
    *hi = packbf2(ha, hb);
    *lo = packbf2(la, lb);
}

// ---------------------------------------------------------------------------
// elementwise fp32 -> bf16 hi plus lo split, n divisible by 4
// ---------------------------------------------------------------------------
__global__ void split_kernel(const float* __restrict__ x,
                             __nv_bfloat16* __restrict__ hi,
                             __nv_bfloat16* __restrict__ lo, int n)
{
    int i = (blockIdx.x * blockDim.x + threadIdx.x) * 4;
    if (i >= n) return;
    float4 v = *(const float4*)(x + i);
    u32 h0, l0, h1, l1;
    split2(v.x, v.y, &h0, &l0);
    split2(v.z, v.w, &h1, &l1);
    u32* hp = (u32*)(hi + i);
    u32* lp = (u32*)(lo + i);
    hp[0] = h0;
    hp[1] = h1;
    lp[0] = l0;
    lp[1] = l1;
}

// ===========================================================================
// bf16-split tensor-core GEMM with pre-split inputs and cp.async pipeline.
// C = A @ B + bias, 3-term split product.
// 128x128 CTA tile, BK 32, 256 threads, 8 warps as 4 row x 2 col,
// double-buffered smem. mode 0 writes fp32 C, mode 1 writes split bf16 C.
// ===========================================================================
#define PA 40
#define PB 136

__device__ __forceinline__ void gemm_stage(
    u32 smem_base, int buf,
    const __nv_bfloat16* Ah, const __nv_bfloat16* Al,
    const __nv_bfloat16* Bh, const __nv_bfloat16* Bl,
    int row0, int col0, int t, int K, int N, int tid)
{
    u32 abase0 = smem_base + (u32)((buf * 2 + 0) * 10240);
    u32 abase1 = smem_base + (u32)((buf * 2 + 1) * 10240);
    u32 bbase0 = smem_base + 40960u + (u32)((buf * 2 + 0) * 8704);
    u32 bbase1 = smem_base + 40960u + (u32)((buf * 2 + 1) * 8704);
#pragma unroll
    for (int c = 0; c < 2; c++) {
        int ch = tid * 2 + c;
        int row = ch >> 2;
        int kc = ch & 3;
        u32 doff = (u32)((row * PA + kc * 8) * 2);
        size_t goff = (size_t)(row0 + row) * K + t * 32 + kc * 8;
        cp16(abase0 + doff, Ah + goff);
        cp16(abase1 + doff, Al + goff);
    }
#pragma unroll
    for (int c = 0; c < 2; c++) {
        int ch = tid * 2 + c;
        int brow = ch >> 4;
        int bc = ch & 15;
        u32 doff = (u32)((brow * PB + bc * 8) * 2);
        size_t goff = (size_t)(t * 32 + brow) * N + col0 + bc * 8;
        cp16(bbase0 + doff, Bh + goff);
        cp16(bbase1 + doff, Bl + goff);
    }
    cp_commit();
}

__global__ __launch_bounds__(256)
void gemm_split_tc(const __nv_bfloat16* __restrict__ Ah,
                   const __nv_bfloat16* __restrict__ Al,
                   const __nv_bfloat16* __restrict__ Bh,
                   const __nv_bfloat16* __restrict__ Bl,
                   const float* __restrict__ bias,
                   float* __restrict__ Cf,
                   __nv_bfloat16* __restrict__ Ch,
                   __nv_bfloat16* __restrict__ Cl,
                   int M, int N, int K, int mode)
{
    extern __shared__ __nv_bfloat16 dsm[];
    u32 smem_base = (u32)__cvta_generic_to_shared(dsm);

    const int tid  = threadIdx.x;
    const int lane = tid & 31;
    const int warp = tid >> 5;
    const int wm   = warp & 3;
    const int wn   = warp >> 2;
    const int row0 = blockIdx.y * 128;
    const int col0 = blockIdx.x * 128;

    float c[2][8][4];
#pragma unroll
    for (int mi = 0; mi < 2; mi++)
#pragma unroll
        for (int j = 0; j < 8; j++)
#pragma unroll
            for (int e = 0; e < 4; e++) c[mi][j][e] = 0.0f;

    const int lrow = lane & 15;
    const int lsel = lane >> 4;
    u32 aoff0 = (u32)(((wm * 32 + lrow) * PA + lsel * 8) * 2);
    u32 aoff1 = (u32)(((wm * 32 + 16 + lrow) * PA + lsel * 8) * 2);
    u32 boff0 = (u32)((lrow * PB + wn * 64 + lsel * 8) * 2);
    u32 boff1 = boff0 + 32;
    u32 boff2 = boff0 + 64;
    u32 boff3 = boff0 + 96;

    const int T = K / 32;

    gemm_stage(smem_base, 0, Ah, Al, Bh, Bl, row0, col0, 0, K, N, tid);

    for (int t = 0; t < T; t++) {
        if (t + 1 < T) {
            gemm_stage(smem_base, (t + 1) & 1, Ah, Al, Bh, Bl,
                       row0, col0, t + 1, K, N, tid);
            cp_wait<1>();
        } else {
            cp_wait<0>();
        }
        __syncthreads();

        const int buf = t & 1;
        u32 sa[2];
        u32 sb[2];
        sa[0] = smem_base + (u32)((buf * 2 + 0) * 10240);
        sa[1] = smem_base + (u32)((buf * 2 + 1) * 10240);
        sb[0] = smem_base + 40960u + (u32)((buf * 2 + 0) * 8704);
        sb[1] = smem_base + 40960u + (u32)((buf * 2 + 1) * 8704);

#pragma unroll
        for (int kk = 0; kk < 2; kk++) {
            u32 afr[2][2][4];
            u32 bfr[2][4][4];
            const u32 ak = (u32)(kk * 32);
            const u32 bk = (u32)(kk * 16 * PB * 2);
#pragma unroll
            for (int h = 0; h < 2; h++) {
                ldsm_x4(afr[h][0], sa[h] + aoff0 + ak);
                ldsm_x4(afr[h][1], sa[h] + aoff1 + ak);
                ldsm_x4_t(bfr[h][0], sb[h] + boff0 + bk);
                ldsm_x4_t(bfr[h][1], sb[h] + boff1 + bk);
                ldsm_x4_t(bfr[h][2], sb[h] + boff2 + bk);
                ldsm_x4_t(bfr[h][3], sb[h] + boff3 + bk);
            }
#pragma unroll
            for (int j = 0; j < 8; j++) {
                const int g = j >> 1;
                const int o = (j & 1) * 2;
#pragma unroll
                for (int mi = 0; mi < 2; mi++) {
                    mma16816(c[mi][j], afr[0][mi], bfr[0][g][o], bfr[0][g][o + 1]);
                    mma16816(c[mi][j], afr[1][mi], bfr[0][g][o], bfr[0][g][o + 1]);
                    mma16816(c[mi][j], afr[0][mi], bfr[1][g][o], bfr[1][g][o + 1]);
                }
            }
        }
        __syncthreads();
    }

    const int crow = lane >> 2;
    const int ccol = (lane & 3) * 2;
#pragma unroll
    for (int j = 0; j < 8; j++) {
        const int col = col0 + wn * 64 + j * 8 + ccol;
        const float2 bb = *(const float2*)(bias + col);
#pragma unroll
        for (int mi = 0; mi < 2; mi++) {
            const int r = row0 + wm * 32 + mi * 16 + crow;
            float x0 = c[mi][j][0] + bb.x;
            float x1 = c[mi][j][1] + bb.y;
            float x2 = c[mi][j][2] + bb.x;
            float x3 = c[mi][j][3] + bb.y;
            if (mode == 0) {
                *(float2*)(Cf + (size_t)r * N + col) = make_float2(x0, x1);
                *(float2*)(Cf + (size_t)(r + 8) * N + col) = make_float2(x2, x3);
            } else {
                u32 hp, lp;
                split2(x0, x1, &hp, &lp);
                *(u32*)(Ch + (size_t)r * N + col) = hp;
                *(u32*)(Cl + (size_t)r * N + col) = lp;
                split2(x2, x3, &hp, &lp);
                *(u32*)(Ch + (size_t)(r + 8) * N + col) = hp;
                *(u32*)(Cl + (size_t)(r + 8) * N + col) = lp;
            }
        }
    }
}

// ===========================================================================
// Tensor-core causal flash attention, bf16 3-term split for QK and PV.
// CTA: one q-tile of 64 rows for one head of one batch. 128 threads, 4 warps,
// each warp owns 16 q rows. K and V tiles of 64 loaded by cp.async.
// ===========================================================================
#define PQ 72

__global__ __launch_bounds__(128)
void attn_tc(const __nv_bfloat16* __restrict__ qh,
             const __nv_bfloat16* __restrict__ ql,
             __nv_bfloat16* __restrict__ oh,
             __nv_bfloat16* __restrict__ ol)
{
    extern __shared__ __nv_bfloat16 dsm[];
    u32 smem_base = (u32)__cvta_generic_to_shared(dsm);

    const int qt  = blockIdx.x;
    const int hh  = blockIdx.y;
    const int b   = blockIdx.z;
    const int tid = threadIdx.x;
    const int lane = tid & 31;
    const int warp = tid >> 5;
    const int q0 = qt * 64;
    const float scale = 0.125f;

    // smem element offsets: Q hi lo, K hi lo, V hi lo, each 64 x PQ
    u32 qb[2];
    u32 kb[2];
    u32 vb[2];
    qb[0] = smem_base;
    qb[1] = smem_base + 9216u;
    kb[0] = smem_base + 18432u;
    kb[1] = smem_base + 27648u;
    vb[0] = smem_base + 36864u;
    vb[1] = smem_base + 46080u;

    // load Q tile once
#pragma unroll
    for (int cc = 0; cc < 4; cc++) {
        int ch = cc * 128 + tid;
        int row = ch >> 3;
        int kc = ch & 7;
        u32 doff = (u32)((row * PQ + kc * 8) * 2);
        size_t goff = (size_t)(b * SEQ + q0 + row) * (3 * DM) + hh * 64 + kc * 8;
        cp16(qb[0] + doff, qh + goff);
        cp16(qb[1] + doff, ql + goff);
    }
    cp_commit();

    float s[8][4];
    float oacc[8][4];
    float m0 = -CUDART_INF_F;
    float m1 = -CUDART_INF_F;
    float den0 = 0.0f;
    float den1 = 0.0f;
#pragma unroll
    for (int j = 0; j < 8; j++)
#pragma unroll
        for (int e = 0; e < 4; e++) oacc[j][e] = 0.0f;

    const int rloc0 = warp * 16 + (lane >> 2);
    const int rloc1 = rloc0 + 8;

    for (int kt = 0; kt <= qt; kt++) {
        __syncthreads();
        // load K and V tiles
#pragma unroll
        for (int cc = 0; cc < 4; cc++) {
            int ch = cc * 128 + tid;
            int row = ch >> 3;
            int kc = ch & 7;
            u32 doff = (u32)((row * PQ + kc * 8) * 2);
            size_t goff = (size_t)(b * SEQ + kt * 64 + row) * (3 * DM)
                        + hh * 64 + kc * 8;
            cp16(kb[0] + doff, qh + goff + DM);
            cp16(kb[1] + doff, ql + goff + DM);
            cp16(vb[0] + doff, qh + goff + 2 * DM);
            cp16(vb[1] + doff, ql + goff + 2 * DM);
        }
        cp_commit();
        cp_wait<0>();
        __syncthreads();

        // S = Q K^T via 3-term split
#pragma unroll
        for (int j = 0; j < 8; j++)
#pragma unroll
            for (int e = 0; e < 4; e++) s[j][e] = 0.0f;

#pragma unroll
        for (int ks = 0; ks < 4; ks++) {
            u32 qa[2][4];
            u32 kfh[4][4];
            u32 kfl[4][4];
            u32 qaddr = (u32)(((warp * 16 + (lane & 15)) * PQ
                               + ks * 16 + (lane >> 4) * 8) * 2);
            ldsm_x4(qa[0], qb[0] + qaddr);
            ldsm_x4(qa[1], qb[1] + qaddr);
#pragma unroll
            for (int g = 0; g < 4; g++) {
                u32 kaddr = (u32)(((g * 16 + (lane & 15)) * PQ
                                   + ks * 16 + (lane >> 4) * 8) * 2);
                ldsm_x4(kfh[g], kb[0] + kaddr);
                ldsm_x4(kfl[g], kb[1] + kaddr);
            }
#pragma unroll
            for (int j = 0; j < 8; j++) {
                const int g = j >> 1;
                const int i0 = j & 1;
                mma16816(s[j], qa[0], kfh[g][i0], kfh[g][i0 + 2]);
                mma16816(s[j], qa[1], kfh[g][i0], kfh[g][i0 + 2]);
                mma16816(s[j], qa[0], kfl[g][i0], kfl[g][i0 + 2]);
            }
        }

        // scale and causal mask
        if (kt == qt) {
#pragma unroll
            for (int j = 0; j < 8; j++) {
                int cb = j * 8 + (lane & 3) * 2;
                s[j][0] = (cb + 0 > rloc0) ? -1e30f : s[j][0] * scale;
                s[j][1] = (cb + 1 > rloc0) ? -1e30f : s[j][1] * scale;
                s[j][2] = (cb + 0 > rloc1) ? -1e30f : s[j][2] * scale;
                s[j][3] = (cb + 1 > rloc1) ? -1e30f : s[j][3] * scale;
            }
        } else {
#pragma unroll
            for (int j = 0; j < 8; j++)
#pragma unroll
                for (int e = 0; e < 4; e++) s[j][e] *= scale;
        }

        // online softmax, rows owned by 4-lane groups
        float rm0 = -1e30f;
        float rm1 = -1e30f;
#pragma unroll
        for (int j = 0; j < 8; j++) {
            rm0 = fmaxf(rm0, fmaxf(s[j][0], s[j][1]));
            rm1 = fmaxf(rm1, fmaxf(s[j][2], s[j][3]));
        }
        rm0 = fmaxf(rm0, __shfl_xor_sync(0xffffffffu, rm0, 1));
        rm0 = fmaxf(rm0, __shfl_xor_sync(0xffffffffu, rm0, 2));
        rm1 = fmaxf(rm1, __shfl_xor_sync(0xffffffffu, rm1, 1));
        rm1 = fmaxf(rm1, __shfl_xor_sync(0xffffffffu, rm1, 2));
        float mn0 = fmaxf(m0, rm0);
        float mn1 = fmaxf(m1, rm1);
        float corr0 = __expf(m0 - mn0);
        float corr1 = __expf(m1 - mn1);
        float ls0 = 0.0f;
        float ls1 = 0.0f;
#pragma unroll
        for (int j = 0; j < 8; j++) {
            s[j][0] = __expf(s[j][0] - mn0);
            s[j][1] = __expf(s[j][1] - mn0);
            s[j][2] = __expf(s[j][2] - mn1);
            s[j][3] = __expf(s[j][3] - mn1);
            ls0 += s[j][0] + s[j][1];
            ls1 += s[j][2] + s[j][3];
        }
        ls0 += __shfl_xor_sync(0xffffffffu, ls0, 1);
        ls0 += __shfl_xor_sync(0xffffffffu, ls0, 2);
        ls1 += __shfl_xor_sync(0xffffffffu, ls1, 1);
        ls1 += __shfl_xor_sync(0xffffffffu, ls1, 2);
        den0 = den0 * corr0 + ls0;
        den1 = den1 * corr1 + ls1;
        m0 = mn0;
        m1 = mn1;
#pragma unroll
        for (int j = 0; j < 8; j++) {
            oacc[j][0] *= corr0;
            oacc[j][1] *= corr0;
            oacc[j][2] *= corr1;
            oacc[j][3] *= corr1;
        }

        // O += P V via 3-term split, P repacked from C frags to A frags
#pragma unroll
        for (int ks = 0; ks < 4; ks++) {
            u32 ah[4];
            u32 al[4];
            split2(s[2 * ks][0], s[2 * ks][1], &ah[0], &al[0]);
            split2(s[2 * ks][2], s[2 * ks][3], &ah[1], &al[1]);
            split2(s[2 * ks + 1][0], s[2 * ks + 1][1], &ah[2], &al[2]);
            split2(s[2 * ks + 1][2], s[2 * ks + 1][3], &ah[3], &al[3]);
            u32 vfh[4][4];
            u32 vfl[4][4];
#pragma unroll
            for (int g = 0; g < 4; g++) {
                u32 vaddr = (u32)(((ks * 16 + (lane & 15)) * PQ
                                   + g * 16 + (lane >> 4) * 8) * 2);
                ldsm_x4_t(vfh[g], vb[0] + vaddr);
                ldsm_x4_t(vfl[g], vb[1] + vaddr);
            }
#pragma unroll
            for (int j = 0; j < 8; j++) {
                const int g = j >> 1;
                const int o = (j & 1) * 2;
                mma16816(oacc[j], ah, vfh[g][o], vfh[g][o + 1]);
                mma16816(oacc[j], al, vfh[g][o], vfh[g][o + 1]);
                mma16816(oacc[j], ah, vfl[g][o], vfl[g][o + 1]);
            }
        }
    }

    // normalize and store split output
    float inv0 = 1.0f / den0;
    float inv1 = 1.0f / den1;
    size_t grow0 = (size_t)(b * SEQ + q0 + rloc0);
    size_t grow1 = grow0 + 8;
#pragma unroll
    for (int j = 0; j < 8; j++) {
        int col = hh * 64 + j * 8 + (lane & 3) * 2;
        u32 hp, lp;
        split2(oacc[j][0] * inv0, oacc[j][1] * inv0, &hp, &lp);
        *(u32*)(oh + grow0 * DM + col) = hp;
        *(u32*)(ol + grow0 * DM + col) = lp;
        split2(oacc[j][2] * inv1, oacc[j][3] * inv1, &hp, &lp);
        *(u32*)(oh + grow1 * DM + col) = hp;
        *(u32*)(ol + grow1 * DM + col) = lp;
    }
}

// ---------------------------------------------------------------------------
// kernel_launch
// ---------------------------------------------------------------------------
extern "C" void kernel_launch(void* const* d_in, const int* in_sizes, int n_in,
                              void* d_out, int out_size)
{
    const float* inp  = (const float*)d_in[0];
    const float* Wqkv = (const float*)d_in[1];
    const float* bqkv = (const float*)d_in[2];
    const float* Wout = (const float*)d_in[3];
    const float* bout = (const float*)d_in[4];
    float* out = (float*)d_out;

    __nv_bfloat16 *inp_h, *inp_l, *wq_h, *wq_l, *wo_h, *wo_l;
    __nv_bfloat16 *qkv_h, *qkv_l, *att_h, *att_l;
    cudaGetSymbolAddress((void**)&inp_h, g_inp_h);
    cudaGetSymbolAddress((void**)&inp_l, g_inp_l);
    cudaGetSymbolAddress((void**)&wq_h, g_wq_h);
    cudaGetSymbolAddress((void**)&wq_l, g_wq_l);
    cudaGetSymbolAddress((void**)&wo_h, g_wo_h);
    cudaGetSymbolAddress((void**)&wo_l, g_wo_l);
    cudaGetSymbolAddress((void**)&qkv_h, g_qkv_h);
    cudaGetSymbolAddress((void**)&qkv_l, g_qkv_l);
    cudaGetSymbolAddress((void**)&att_h, g_att_h);
    cudaGetSymbolAddress((void**)&att_l, g_att_l);

    const int smem_gemm = 75776;
    const int smem_attn = 55296;
    cudaFuncSetAttribute(gemm_split_tc,
                         cudaFuncAttributeMaxDynamicSharedMemorySize, smem_gemm);
    cudaFuncSetAttribute(attn_tc,
                         cudaFuncAttributeMaxDynamicSharedMemorySize, smem_attn);

    // pre-split inputs and weights
    {
        int n1 = MROWS * DM;
        split_kernel<<<n1 / 1024, 256>>>(inp, inp_h, inp_l, n1);
        int n2 = DM * 3 * DM;
        split_kernel<<<n2 / 1024, 256>>>(Wqkv, wq_h, wq_l, n2);
        int n3 = DM * DM;
        split_kernel<<<n3 / 1024, 256>>>(Wout, wo_h, wo_l, n3);
    }

    // qkv projection, split bf16 output
    dim3 g1(3 * DM / 128, MROWS / 128);
    gemm_split_tc<<<g1, 256, smem_gemm>>>(inp_h, inp_l, wq_h, wq_l, bqkv,
                                          (float*)0, qkv_h, qkv_l,
                                          MROWS, 3 * DM, DM, 1);

    // causal attention, split bf16 output
    dim3 gf(SEQ / 64, NHEAD, BATCH);
    attn_tc<<<gf, 128, smem_attn>>>(qkv_h, qkv_l, att_h, att_l);

    // output projection, fp32 output
    dim3 g2(DM / 128, MROWS / 128);
    gemm_split_tc<<<g2, 256, smem_gemm>>>(att_h, att_l, wo_h, wo_l, bout,
                                          out, (__nv_bfloat16*)0, (__nv_bfloat16*)0,
                                          MROWS, DM, DM, 0);
}